// round 10
// baseline (speedup 1.0000x reference)
#include <cuda_runtime.h>
#include <math.h>

#define N_NODES 200000
#define N_EDGES 1000000
#define HDIM    64
#define NGRAPH  512
#define NCLS    10
#define BN_EPS  1e-5f

#define SCAN_CHUNK 1024
#define SCAN_BLKS  ((N_NODES + SCAN_CHUNK - 1) / SCAN_CHUNK)   // 196
#define NBUCKET 64
#define PSUM_STRIDE (NBUCKET * 2 * HDIM)            // 8192 doubles per layer
#define ADJ_TOTAL (N_EDGES + 3 * N_NODES)           // 1.6M, padded adjacency

typedef unsigned long long ull;
#define PACK2(d, x)   asm("mov.b64 %0, {%1, %1};" : "=l"(d) : "f"(x))
#define FMA2(d, a, b) asm("fma.rn.f32x2 %0, %1, %2, %0;" : "+l"(d) : "l"(a), "l"(b))
#define MUL2(d, a, b) asm("mul.rn.f32x2 %0, %1, %2;" : "=l"(d) : "l"(a), "l"(b))

// ---------------- static device scratch ----------------
__device__ __align__(256) float  g_buf1[(size_t)(N_NODES + 1) * HDIM]; // h' (row N = 0)
__device__ __align__(256) float  g_buf2[(size_t)N_NODES * HDIM];       // AGG layer 1
__device__ __align__(256) float  g_buf3[(size_t)N_NODES * HDIM];       // AGG layer 2
__device__ __align__(256) int    g_adj[ADJ_TOTAL];
__device__ __align__(256) int    g_cnt[N_NODES];
__device__ __align__(256) int2   g_row2[N_NODES];                      // {rowstart, cnt_padded}
__device__ __align__(256) int    g_cursor[N_NODES];
__device__ __align__(256) int    g_localex[N_NODES];
__device__ __align__(16)  int    g_blksum[256];
__device__ __align__(256) float  g_dinv[N_NODES];
__device__ __align__(256) double g_psums[2 * PSUM_STRIDE];
__device__ __align__(16)  float  g_scale[HDIM];
__device__ __align__(16)  float  g_shift[HDIM];
__device__ __align__(256) float  g_pool1[NGRAPH * HDIM];               // relu1 partial sums
__device__ int g_done;

// ---------------- init: dummy-fill adj (int4), zero everything ----------------
__global__ void init_kernel(int4* __restrict__ adj4, int* __restrict__ cnt,
                            double* __restrict__ psums, float* __restrict__ pool1,
                            float* __restrict__ buf1, int* __restrict__ done) {
    int i = blockIdx.x * blockDim.x + threadIdx.x;
    if (i < ADJ_TOTAL / 4) adj4[i] = make_int4(N_NODES, N_NODES, N_NODES, N_NODES);
    if (i < N_NODES) cnt[i] = 0;
    if (i < 2 * PSUM_STRIDE) psums[i] = 0.0;
    if (i < NGRAPH * HDIM) pool1[i] = 0.0f;
    if (i < HDIM) buf1[(size_t)N_NODES * HDIM + i] = 0.0f;  // zero row for dummies
    if (i == 0) *done = 0;
}

__global__ void deg_count_kernel(const int* __restrict__ dst, int* __restrict__ cnt) {
    int i = blockIdx.x * blockDim.x + threadIdx.x;
    if (i >= N_EDGES / 4) return;
    int4 d = __ldg((const int4*)dst + i);
    atomicAdd(&cnt[d.x], 1);
    atomicAdd(&cnt[d.y], 1);
    atomicAdd(&cnt[d.z], 1);
    atomicAdd(&cnt[d.w], 1);
}

__global__ void dinv_kernel(const int* __restrict__ cnt, float* __restrict__ dinv) {
    int i = blockIdx.x * blockDim.x + threadIdx.x;
    if (i < N_NODES) dinv[i] = rsqrtf((float)(cnt[i] + 1));
}

// ---------------- scan over PADDED counts ----------------
__global__ void scanA_kernel(const int* __restrict__ cnt, int* __restrict__ localex,
                             int* __restrict__ blksum) {
    __shared__ int sh[256];
    int b = blockIdx.x, t = threadIdx.x;
    int base = b * SCAN_CHUNK + t * 4;
    int v0 = (base + 0 < N_NODES) ? ((cnt[base + 0] + 3) & ~3) : 0;
    int v1 = (base + 1 < N_NODES) ? ((cnt[base + 1] + 3) & ~3) : 0;
    int v2 = (base + 2 < N_NODES) ? ((cnt[base + 2] + 3) & ~3) : 0;
    int v3 = (base + 3 < N_NODES) ? ((cnt[base + 3] + 3) & ~3) : 0;
    int s = v0 + v1 + v2 + v3;
    sh[t] = s;
    __syncthreads();
#pragma unroll
    for (int off = 1; off < 256; off <<= 1) {
        int x = (t >= off) ? sh[t - off] : 0;
        __syncthreads();
        sh[t] += x;
        __syncthreads();
    }
    int excl = sh[t] - s;
    if (t == 255) blksum[b] = sh[255];
    if (base + 0 < N_NODES) localex[base + 0] = excl;  excl += v0;
    if (base + 1 < N_NODES) localex[base + 1] = excl;  excl += v1;
    if (base + 2 < N_NODES) localex[base + 2] = excl;  excl += v2;
    if (base + 3 < N_NODES) localex[base + 3] = excl;
}

__global__ void scanC_kernel(const int* __restrict__ localex, const int* __restrict__ blksum,
                             const int* __restrict__ cnt,
                             int2* __restrict__ row2, int* __restrict__ cursor) {
    __shared__ int sh[256];
    __shared__ int pre[256];
    int t = threadIdx.x;
    int v = (t < SCAN_BLKS) ? blksum[t] : 0;
    sh[t] = v;
    __syncthreads();
#pragma unroll
    for (int off = 1; off < 256; off <<= 1) {
        int x = (t >= off) ? sh[t - off] : 0;
        __syncthreads();
        sh[t] += x;
        __syncthreads();
    }
    pre[t] = sh[t] - v;
    __syncthreads();

    int i = blockIdx.x * 256 + t;
    if (i < N_NODES) {
        int c = cnt[i];
        int r = localex[i] + pre[i >> 10];
        row2[i] = make_int2(r, (c + 3) & ~3);
        cursor[i] = r;
    }
}

__global__ void scatter_kernel(const int* __restrict__ src, const int* __restrict__ dst,
                               int* __restrict__ cursor, int* __restrict__ adj) {
    int i = blockIdx.x * blockDim.x + threadIdx.x;
    if (i >= N_EDGES / 4) return;
    int4 s = __ldg((const int4*)src + i);
    int4 d = __ldg((const int4*)dst + i);
    adj[atomicAdd(&cursor[d.x], 1)] = s.x;
    adj[atomicAdd(&cursor[d.y], 1)] = s.y;
    adj[atomicAdd(&cursor[d.z], 1)] = s.z;
    adj[atomicAdd(&cursor[d.w], 1)] = s.w;
}

// ---------------- 64x64 GEMM, f32x2 packed FMA, 4x8 per thread ----------------
// 128 threads: tr = tid>>3 (rows 4tr..4tr+3), tc = tid&7 (cols 8tc..8tc+7).
// Output h' = (X@W) * dinv[row]. FUSED: relu(BN1(X)) on load + residual pooling.
template <bool FUSED>
__global__ void __launch_bounds__(128) gemm64_kernel(
        const float* __restrict__ X, const float* __restrict__ W,
        const float* __restrict__ dinv,
        const float* __restrict__ scale, const float* __restrict__ shift,
        const int* __restrict__ batch, float* __restrict__ pool1,
        float* __restrict__ HP) {
    __shared__ __align__(16) float Ws[64 * 64];   // [k][col]
    __shared__ __align__(16) float Xt[64 * 68];   // [k][row]
    __shared__ float Ds[64];
    __shared__ int sbatch[64];

    int tid  = threadIdx.x;
    int row0 = blockIdx.x * 64;

    const float4* W4 = (const float4*)W;
#pragma unroll
    for (int j = 0; j < 8; j++)
        ((float4*)Ws)[tid + j * 128] = W4[tid + j * 128];

    const float4* X4 = (const float4*)(X + (size_t)row0 * 64);
    int rot = tid & 3;
#pragma unroll
    for (int j = 0; j < 8; j++) {
        int idx4 = tid + j * 128;
        int r = idx4 >> 4, c4 = idx4 & 15;
        float4 v = X4[idx4];
        if (FUSED) {
            float4 sc = ((const float4*)scale)[c4];
            float4 sh = ((const float4*)shift)[c4];
            v.x = fmaxf(fmaf(v.x, sc.x, sh.x), 0.0f);
            v.y = fmaxf(fmaf(v.y, sc.y, sh.y), 0.0f);
            v.z = fmaxf(fmaf(v.z, sc.z, sh.z), 0.0f);
            v.w = fmaxf(fmaf(v.w, sc.w, sh.w), 0.0f);
        }
#pragma unroll
        for (int i = 0; i < 4; i++) {   // lane-rotated transpose store (breaks conflicts)
            int ii = (i + rot) & 3;
            float e = (ii == 0) ? v.x : (ii == 1) ? v.y : (ii == 2) ? v.z : v.w;
            Xt[(4 * c4 + ii) * 68 + r] = e;
        }
    }
    if (tid < 64) {
        Ds[tid] = dinv[row0 + tid];
        if (FUSED) sbatch[tid] = batch[row0 + tid];
    }
    __syncthreads();

    int tr = tid >> 3, tc = tid & 7;
    ull acc[4][4];
#pragma unroll
    for (int i = 0; i < 4; i++)
#pragma unroll
        for (int j = 0; j < 4; j++) acc[i][j] = 0ULL;

#pragma unroll 8
    for (int k = 0; k < 64; k++) {
        float4 xv = *(const float4*)&Xt[k * 68 + 4 * tr];
        ull xp0, xp1, xp2, xp3;
        PACK2(xp0, xv.x); PACK2(xp1, xv.y); PACK2(xp2, xv.z); PACK2(xp3, xv.w);
        ulonglong2 wA = *(const ulonglong2*)&Ws[k * 64 + 8 * tc];
        ulonglong2 wB = *(const ulonglong2*)&Ws[k * 64 + 8 * tc + 4];
        FMA2(acc[0][0], xp0, wA.x); FMA2(acc[0][1], xp0, wA.y);
        FMA2(acc[0][2], xp0, wB.x); FMA2(acc[0][3], xp0, wB.y);
        FMA2(acc[1][0], xp1, wA.x); FMA2(acc[1][1], xp1, wA.y);
        FMA2(acc[1][2], xp1, wB.x); FMA2(acc[1][3], xp1, wB.y);
        FMA2(acc[2][0], xp2, wA.x); FMA2(acc[2][1], xp2, wA.y);
        FMA2(acc[2][2], xp2, wB.x); FMA2(acc[2][3], xp2, wB.y);
        FMA2(acc[3][0], xp3, wA.x); FMA2(acc[3][1], xp3, wA.y);
        FMA2(acc[3][2], xp3, wB.x); FMA2(acc[3][3], xp3, wB.y);
    }

#pragma unroll
    for (int i = 0; i < 4; i++) {
        int r = 4 * tr + i;
        ull dp; PACK2(dp, Ds[r]);
        ull o0, o1, o2, o3;
        MUL2(o0, acc[i][0], dp); MUL2(o1, acc[i][1], dp);
        MUL2(o2, acc[i][2], dp); MUL2(o3, acc[i][3], dp);
        ulonglong2* outp = (ulonglong2*)&HP[(size_t)(row0 + r) * 64 + 8 * tc];
        outp[0] = make_ulonglong2(o0, o1);
        outp[1] = make_ulonglong2(o2, o3);
    }

    if (FUSED) {   // residual pooling of relu1 rows (batch sorted); Xt[f][r] holds relu1
        int f = tid & 63;
        int q = tid >> 6;   // 0..1, each group handles 32 rows
        float s = 0.0f;
        int curg = sbatch[q * 32];
#pragma unroll 4
        for (int rr = 0; rr < 32; rr++) {
            int r = q * 32 + rr;
            int gg = sbatch[r];
            if (gg != curg) { atomicAdd(&pool1[curg * 64 + f], s); s = 0.0f; curg = gg; }
            s += Xt[f * 68 + r];
        }
        atomicAdd(&pool1[curg * 64 + f], s);
    }
}

// ---------------- CSR gather agg + fused BN stats (+last-block finalize) ----------------
template <bool FINALIZE>
__global__ void __launch_bounds__(256) agg_kernel(
        const int2* __restrict__ row2, const int* __restrict__ adj,
        const float* __restrict__ dinv,
        const float* __restrict__ HP, float* __restrict__ AGG,
        double* __restrict__ psums, int* __restrict__ done,
        const float* __restrict__ gw, const float* __restrict__ be,
        float* __restrict__ scale, float* __restrict__ shift) {
    int tid  = threadIdx.x;
    int node = blockIdx.x * 16 + (tid >> 4);
    int part = tid & 15;
    const float4* Hp = (const float4*)HP;

    float4 acc = __ldg(Hp + (size_t)node * 16 + part);   // self h'[d]
    int2 rc = __ldg(row2 + node);
    const int4* ap = (const int4*)(adj + rc.x);          // beg % 4 == 0 -> aligned
    int nIt = rc.y >> 2;
    for (int it = 0; it < nIt; it++) {
        int4 s4 = __ldg(ap + it);
        float4 a = __ldg(Hp + (size_t)s4.x * 16 + part);
        float4 b = __ldg(Hp + (size_t)s4.y * 16 + part);
        float4 c = __ldg(Hp + (size_t)s4.z * 16 + part);
        float4 e = __ldg(Hp + (size_t)s4.w * 16 + part);
        acc.x += (a.x + b.x) + (c.x + e.x);
        acc.y += (a.y + b.y) + (c.y + e.y);
        acc.z += (a.z + b.z) + (c.z + e.z);
        acc.w += (a.w + b.w) + (c.w + e.w);
    }
    float dd = __ldg(dinv + node);
    acc.x *= dd; acc.y *= dd; acc.z *= dd; acc.w *= dd;
    ((float4*)AGG)[(size_t)node * 16 + part] = acc;

    __shared__ float4 s_acc[256];
    s_acc[tid] = acc;
    __syncthreads();
    if (tid < HDIM) {
        const float* sa = (const float*)s_acc;
        float s = 0.0f, sq = 0.0f;
#pragma unroll
        for (int n = 0; n < 16; n++) {
            float v = sa[n * 64 + tid];
            s += v;
            sq += v * v;
        }
        int bucket = blockIdx.x & (NBUCKET - 1);
        atomicAdd(&psums[bucket * 128 + tid], (double)s);
        atomicAdd(&psums[bucket * 128 + HDIM + tid], (double)sq);
    }

    if (FINALIZE) {
        __shared__ int islast;
        __threadfence();
        __syncthreads();
        if (tid == 0) islast = (atomicAdd(done, 1) == (int)gridDim.x - 1);
        __syncthreads();
        if (islast && tid < HDIM) {
            __threadfence();
            int f = tid;
            double s = 0.0, sq = 0.0;
#pragma unroll 4
            for (int b = 0; b < NBUCKET; b++) {
                s  += psums[b * 128 + f];
                sq += psums[b * 128 + HDIM + f];
            }
            double mean = s / (double)N_NODES;
            double var  = sq / (double)N_NODES - mean * mean;
            float rs = rsqrtf((float)var + BN_EPS);
            float scv = rs * gw[f];
            scale[f] = scv;
            shift[f] = (float)(-mean) * scv + be[f];
        }
    }
}

// ---------------- fused: BN2-finalize + BN2 apply + pool2 + residual pool1 + head ------
__global__ void __launch_bounds__(512) poolhead_kernel(
        const float* __restrict__ AGG2, const float* __restrict__ pool1,
        const double* __restrict__ psums2,
        const float* __restrict__ g2, const float* __restrict__ be2,
        const int* __restrict__ batch,
        const float* __restrict__ lw1, const float* __restrict__ lb1,
        const float* __restrict__ lw2, const float* __restrict__ lb2,
        float* __restrict__ out) {
    int g = blockIdx.x;
    int tid = threadIdx.x;

    __shared__ float sc2s[64], sh2s[64];
    __shared__ int s_start, s_end;

    if (tid >= 64 && tid < 128) {
        int f = tid - 64;
        double s = 0.0, sq = 0.0;
#pragma unroll 4
        for (int b = 0; b < NBUCKET; b++) {
            s  += psums2[b * 128 + f];
            sq += psums2[b * 128 + HDIM + f];
        }
        double mean = s / (double)N_NODES;
        double var  = sq / (double)N_NODES - mean * mean;
        float rs = rsqrtf((float)var + BN_EPS);
        float sc = rs * g2[f];
        sc2s[f] = sc;
        sh2s[f] = (float)(-mean) * sc + be2[f];
    }
    if (tid == 0) {
        int lo = 0, hi = N_NODES;
        while (lo < hi) { int mid = (lo + hi) >> 1; if (batch[mid] < g) lo = mid + 1; else hi = mid; }
        s_start = lo;
        hi = N_NODES;
        while (lo < hi) { int mid = (lo + hi) >> 1; if (batch[mid] < g + 1) lo = mid + 1; else hi = mid; }
        s_end = lo;
    }
    __syncthreads();

    int start = s_start, end = s_end;
    int f = tid & 63;
    int grp = tid >> 6;
    float sc2 = sc2s[f], sh2 = sh2s[f];
    float s = 0.0f;
#pragma unroll 2
    for (int r = start + grp; r < end; r += 8) {
        float a2 = AGG2[(size_t)r * 64 + f];
        s += fmaxf(fmaf(a2, sc2, sh2), 0.0f);
    }
    __shared__ float shm[512];
    shm[tid] = s;
    __syncthreads();

    __shared__ float p[64];
    if (grp == 0) {
        float t = 0.0f;
#pragma unroll
        for (int q = 0; q < 8; q++) t += shm[f + q * 64];
        t += __ldg(pool1 + g * 64 + f);
        int cnt = end - start;
        p[f] = t / (float)(cnt > 0 ? cnt : 1);
    }
    __syncthreads();

    __shared__ float z[32];
    __shared__ float lg[NCLS];
    if (tid < 32) {
        float acc = lb1[tid];
#pragma unroll
        for (int k = 0; k < 64; k++) acc += p[k] * lw1[k * 32 + tid];
        z[tid] = fmaxf(acc, 0.0f);
    }
    __syncthreads();
    if (tid < NCLS) {
        float acc = lb2[tid];
#pragma unroll
        for (int k = 0; k < 32; k++) acc += z[k] * lw2[k * 10 + tid];
        lg[tid] = acc;
    }
    __syncthreads();
    if (tid == 0) {
        float m = lg[0];
#pragma unroll
        for (int c = 1; c < NCLS; c++) m = fmaxf(m, lg[c]);
        float se = 0.0f;
#pragma unroll
        for (int c = 0; c < NCLS; c++) se += expf(lg[c] - m);
        float l = m + logf(se);
#pragma unroll
        for (int c = 0; c < NCLS; c++) out[g * NCLS + c] = lg[c] - l;
    }
}

// ---------------- host ----------------
extern "C" void kernel_launch(void* const* d_in, const int* in_sizes, int n_in,
                              void* d_out, int out_size) {
    const float* x     = (const float*)d_in[0];
    const int*   ei    = (const int*)  d_in[1];
    const int*   batch = (const int*)  d_in[2];
    const float* W1  = (const float*)d_in[3];
    // b1 (d_in[4]) cancels inside BatchNorm
    const float* g1  = (const float*)d_in[5];
    const float* be1 = (const float*)d_in[6];
    const float* W2  = (const float*)d_in[7];
    // b2 (d_in[8]) cancels
    const float* g2  = (const float*)d_in[9];
    const float* be2 = (const float*)d_in[10];
    const float* lw1 = (const float*)d_in[11];
    const float* lb1 = (const float*)d_in[12];
    const float* lw2 = (const float*)d_in[13];
    const float* lb2 = (const float*)d_in[14];

    const int* src = ei;
    const int* dst = ei + N_EDGES;

    float *buf1, *buf2, *buf3, *dinv, *scale, *shift, *pool1;
    int *adj, *cnt, *cursor, *localex, *blksum, *done;
    int2* row2;
    double* psums;
    cudaGetSymbolAddress((void**)&buf1,   g_buf1);
    cudaGetSymbolAddress((void**)&buf2,   g_buf2);
    cudaGetSymbolAddress((void**)&buf3,   g_buf3);
    cudaGetSymbolAddress((void**)&adj,    g_adj);
    cudaGetSymbolAddress((void**)&cnt,    g_cnt);
    cudaGetSymbolAddress((void**)&row2,   g_row2);
    cudaGetSymbolAddress((void**)&cursor, g_cursor);
    cudaGetSymbolAddress((void**)&localex,g_localex);
    cudaGetSymbolAddress((void**)&blksum, g_blksum);
    cudaGetSymbolAddress((void**)&dinv,   g_dinv);
    cudaGetSymbolAddress((void**)&psums,  g_psums);
    cudaGetSymbolAddress((void**)&scale,  g_scale);
    cudaGetSymbolAddress((void**)&shift,  g_shift);
    cudaGetSymbolAddress((void**)&pool1,  g_pool1);
    cudaGetSymbolAddress((void**)&done,   g_done);

    const int TB = 256;
    const int init_blk = (ADJ_TOTAL / 4 + TB - 1) / TB;  // 1563
    const int n_blk    = (N_NODES + TB - 1) / TB;        // 782
    const int e4_blk   = (N_EDGES / 4 + TB - 1) / TB;    // 977
    const int agg_blk  = N_NODES / 16;                   // 12500
    const int gemm_blk = N_NODES / 64;                   // 3125

    // ---- degrees first so gemm1 (launch idx 3 = profile slot) can scale by dinv ----
    init_kernel     <<<init_blk, TB>>>((int4*)adj, cnt, psums, pool1, buf1, done);
    deg_count_kernel<<<e4_blk, TB>>>(dst, cnt);
    dinv_kernel     <<<n_blk, TB>>>(cnt, dinv);
    gemm64_kernel<false><<<gemm_blk, 128>>>(x, W1, dinv, nullptr, nullptr,
                                            nullptr, nullptr, buf1);
    scanA_kernel    <<<SCAN_BLKS, 256>>>(cnt, localex, blksum);
    scanC_kernel    <<<n_blk, 256>>>(localex, blksum, cnt, row2, cursor);
    scatter_kernel  <<<e4_blk, TB>>>(src, dst, cursor, adj);

    // ---- layer 1: agg + BN stats + last-block finalize ----
    agg_kernel<true><<<agg_blk, TB>>>(row2, adj, dinv, buf1, buf2, psums, done,
                                      g1, be1, scale, shift);

    // ---- layer 2: BN1+relu fused on input, residual pooling fused ----
    gemm64_kernel<true><<<gemm_blk, 128>>>(buf2, W2, dinv, scale, shift,
                                           batch, pool1, buf1);
    agg_kernel<false><<<agg_blk, TB>>>(row2, adj, dinv, buf1, buf3, psums + PSUM_STRIDE,
                                       nullptr, nullptr, nullptr, nullptr, nullptr);

    // ---- fused BN2-finalize + apply + pool + head ----
    poolhead_kernel<<<NGRAPH, 512>>>(buf3, pool1, psums + PSUM_STRIDE,
                                     g2, be2, batch, lw1, lb1, lw2, lb2, (float*)d_out);
}

// round 11
// speedup vs baseline: 1.1979x; 1.1979x over previous
#include <cuda_runtime.h>
#include <math.h>

#define N_NODES 200000
#define N_EDGES 1000000
#define HDIM    64
#define NGRAPH  512
#define NCLS    10
#define BN_EPS  1e-5f

#define SCAN_CHUNK 1024
#define SCAN_BLKS  ((N_NODES + SCAN_CHUNK - 1) / SCAN_CHUNK)   // 196
#define NBUCKET 64
#define PSUM_STRIDE (NBUCKET * 2 * HDIM)            // 8192 doubles per layer
#define ADJ_TOTAL (N_EDGES + 3 * N_NODES)           // 1.6M padded adjacency capacity

// ---------------- static device scratch ----------------
__device__ __align__(256) float  g_buf1[(size_t)(N_NODES + 1) * HDIM]; // h' (row N = 0)
__device__ __align__(256) float  g_buf2[(size_t)N_NODES * HDIM];       // AGG layer 1
__device__ __align__(256) float  g_buf3[(size_t)N_NODES * HDIM];       // AGG layer 2
__device__ __align__(256) int    g_adj[ADJ_TOTAL];
__device__ __align__(256) int    g_cnt[N_NODES];
__device__ __align__(256) int2   g_row2[N_NODES];                      // {rowstart, cnt_padded}
__device__ __align__(256) int    g_cursor[N_NODES];
__device__ __align__(256) int    g_localex[N_NODES];
__device__ __align__(16)  int    g_blksum[256];
__device__ __align__(256) float  g_dinv[N_NODES];
__device__ __align__(256) double g_psums[2 * PSUM_STRIDE];             // [layer][bucket][128]
__device__ __align__(16)  float  g_scale[HDIM];
__device__ __align__(16)  float  g_shift[HDIM];

// ---------------- init: dummy-fill adj, zero counts/psums/zero-row ----------------
__global__ void init_kernel(int4* __restrict__ adj4, int* __restrict__ cnt,
                            double* __restrict__ psums, float* __restrict__ buf1) {
    int i = blockIdx.x * blockDim.x + threadIdx.x;
    if (i < ADJ_TOTAL / 4) adj4[i] = make_int4(N_NODES, N_NODES, N_NODES, N_NODES);
    if (i < N_NODES) cnt[i] = 0;
    if (i < 2 * PSUM_STRIDE) psums[i] = 0.0;
    if (i < HDIM) buf1[(size_t)N_NODES * HDIM + i] = 0.0f;  // zero row for dummies
}

__global__ void deg_count_kernel(const int* __restrict__ dst, int* __restrict__ cnt) {
    int i = blockIdx.x * blockDim.x + threadIdx.x;
    if (i >= N_EDGES / 4) return;
    int4 d = __ldg((const int4*)dst + i);
    atomicAdd(&cnt[d.x], 1);
    atomicAdd(&cnt[d.y], 1);
    atomicAdd(&cnt[d.z], 1);
    atomicAdd(&cnt[d.w], 1);
}

// ---------------- scan over PADDED counts ----------------
__global__ void scanA_kernel(const int* __restrict__ cnt, int* __restrict__ localex,
                             int* __restrict__ blksum) {
    __shared__ int sh[256];
    int b = blockIdx.x, t = threadIdx.x;
    int base = b * SCAN_CHUNK + t * 4;
    int v0 = (base + 0 < N_NODES) ? ((cnt[base + 0] + 3) & ~3) : 0;
    int v1 = (base + 1 < N_NODES) ? ((cnt[base + 1] + 3) & ~3) : 0;
    int v2 = (base + 2 < N_NODES) ? ((cnt[base + 2] + 3) & ~3) : 0;
    int v3 = (base + 3 < N_NODES) ? ((cnt[base + 3] + 3) & ~3) : 0;
    int s = v0 + v1 + v2 + v3;
    sh[t] = s;
    __syncthreads();
#pragma unroll
    for (int off = 1; off < 256; off <<= 1) {
        int x = (t >= off) ? sh[t - off] : 0;
        __syncthreads();
        sh[t] += x;
        __syncthreads();
    }
    int excl = sh[t] - s;
    if (t == 255) blksum[b] = sh[255];
    if (base + 0 < N_NODES) localex[base + 0] = excl;  excl += v0;
    if (base + 1 < N_NODES) localex[base + 1] = excl;  excl += v1;
    if (base + 2 < N_NODES) localex[base + 2] = excl;  excl += v2;
    if (base + 3 < N_NODES) localex[base + 3] = excl;
}

// each block redundantly scans blksum, then finalizes its 256 nodes
__global__ void scanC_kernel(const int* __restrict__ localex, const int* __restrict__ blksum,
                             const int* __restrict__ cnt,
                             int2* __restrict__ row2, int* __restrict__ cursor,
                             float* __restrict__ dinv) {
    __shared__ int sh[256];
    __shared__ int pre[256];
    int t = threadIdx.x;
    int v = (t < SCAN_BLKS) ? blksum[t] : 0;
    sh[t] = v;
    __syncthreads();
#pragma unroll
    for (int off = 1; off < 256; off <<= 1) {
        int x = (t >= off) ? sh[t - off] : 0;
        __syncthreads();
        sh[t] += x;
        __syncthreads();
    }
    pre[t] = sh[t] - v;
    __syncthreads();

    int i = blockIdx.x * 256 + t;
    if (i < N_NODES) {
        int c = cnt[i];
        int r = localex[i] + pre[i >> 10];
        row2[i] = make_int2(r, (c + 3) & ~3);   // padded count
        cursor[i] = r;
        dinv[i] = rsqrtf((float)(c + 1));
    }
}

__global__ void scatter_kernel(const int* __restrict__ src, const int* __restrict__ dst,
                               int* __restrict__ cursor, int* __restrict__ adj) {
    int i = blockIdx.x * blockDim.x + threadIdx.x;
    if (i >= N_EDGES / 4) return;
    int4 s = __ldg((const int4*)src + i);
    int4 d = __ldg((const int4*)dst + i);
    adj[atomicAdd(&cursor[d.x], 1)] = s.x;
    adj[atomicAdd(&cursor[d.y], 1)] = s.y;
    adj[atomicAdd(&cursor[d.z], 1)] = s.z;
    adj[atomicAdd(&cursor[d.w], 1)] = s.w;
}

// ---------------- 64x64 GEMM, 4x4 register tiles (R7 champion config) ----------------
// 256 threads = 16x16; thread (tr,tc) computes rows 4tr..+3, cols 4tc..+3.
template <bool APPLY_BN>
__global__ void __launch_bounds__(256) gemm64_kernel(
        const float* __restrict__ X, const float* __restrict__ W,
        const float* __restrict__ dinv,
        const float* __restrict__ scale, const float* __restrict__ shift,
        float* __restrict__ HP) {
    __shared__ __align__(16) float Ws[64 * 64];   // [k][col]
    __shared__ __align__(16) float Xt[64 * 68];   // [k][row], stride 68 (16B-aligned rows)
    __shared__ float Ds[64];

    int tid  = threadIdx.x;
    int row0 = blockIdx.x * 64;

    float sc = 1.0f, sh = 0.0f;
    if (APPLY_BN) {
        sc = __ldg(scale + (tid & 63));
        sh = __ldg(shift + (tid & 63));
    }

#pragma unroll
    for (int j = 0; j < 16; j++) Ws[tid + j * 256] = W[tid + j * 256];
#pragma unroll
    for (int j = 0; j < 16; j++) {
        int idx = tid + j * 256;
        float v = X[(size_t)row0 * 64 + idx];
        if (APPLY_BN) v = fmaxf(fmaf(v, sc, sh), 0.0f);
        Xt[(idx & 63) * 68 + (idx >> 6)] = v;   // transpose: Xt[k][row]
    }
    if (tid < 64) Ds[tid] = dinv[row0 + tid];
    __syncthreads();

    int tr = tid >> 4, tc = tid & 15;
    float acc[4][4];
#pragma unroll
    for (int i = 0; i < 4; i++)
#pragma unroll
        for (int j = 0; j < 4; j++) acc[i][j] = 0.0f;

#pragma unroll
    for (int k = 0; k < 64; k++) {
        float4 xv = *(const float4*)&Xt[k * 68 + 4 * tr];
        float4 wv = *(const float4*)&Ws[k * 64 + 4 * tc];
        acc[0][0] += xv.x * wv.x; acc[0][1] += xv.x * wv.y; acc[0][2] += xv.x * wv.z; acc[0][3] += xv.x * wv.w;
        acc[1][0] += xv.y * wv.x; acc[1][1] += xv.y * wv.y; acc[1][2] += xv.y * wv.z; acc[1][3] += xv.y * wv.w;
        acc[2][0] += xv.z * wv.x; acc[2][1] += xv.z * wv.y; acc[2][2] += xv.z * wv.z; acc[2][3] += xv.z * wv.w;
        acc[3][0] += xv.w * wv.x; acc[3][1] += xv.w * wv.y; acc[3][2] += xv.w * wv.z; acc[3][3] += xv.w * wv.w;
    }

#pragma unroll
    for (int i = 0; i < 4; i++) {
        int r = 4 * tr + i;
        float d = Ds[r];
        float4 o;
        o.x = acc[i][0] * d; o.y = acc[i][1] * d;
        o.z = acc[i][2] * d; o.w = acc[i][3] * d;
        *(float4*)&HP[(size_t)(row0 + r) * 64 + 4 * tc] = o;
    }
}

// ---------------- CSR gather agg (padded, int4 idx) + fused BN stats ----------------
__global__ void __launch_bounds__(256) agg_kernel(
        const int2* __restrict__ row2, const int* __restrict__ adj,
        const float* __restrict__ dinv,
        const float* __restrict__ HP, float* __restrict__ AGG,
        double* __restrict__ psums) {
    int tid  = threadIdx.x;
    int node = blockIdx.x * 16 + (tid >> 4);
    int part = tid & 15;
    const float4* Hp = (const float4*)HP;

    float4 acc = __ldg(Hp + (size_t)node * 16 + part);   // self h'[d] (pre-scaled by dinv)
    int2 rc = __ldg(row2 + node);
    const int4* ap = (const int4*)(adj + rc.x);           // rowstart % 4 == 0 -> aligned
    int nIt = rc.y >> 2;
    for (int it = 0; it < nIt; it++) {
        int4 s4 = __ldg(ap + it);
        float4 a = __ldg(Hp + (size_t)s4.x * 16 + part);
        float4 b = __ldg(Hp + (size_t)s4.y * 16 + part);
        float4 c = __ldg(Hp + (size_t)s4.z * 16 + part);
        float4 e = __ldg(Hp + (size_t)s4.w * 16 + part);
        acc.x += (a.x + b.x) + (c.x + e.x);
        acc.y += (a.y + b.y) + (c.y + e.y);
        acc.z += (a.z + b.z) + (c.z + e.z);
        acc.w += (a.w + b.w) + (c.w + e.w);
    }
    float dd = __ldg(dinv + node);
    acc.x *= dd; acc.y *= dd; acc.z *= dd; acc.w *= dd;
    ((float4*)AGG)[(size_t)node * 16 + part] = acc;

    // fused BN stats: block-reduce over 16 nodes, bucketed double atomics
    __shared__ float4 s_acc[256];
    s_acc[tid] = acc;
    __syncthreads();
    if (tid < HDIM) {
        const float* sa = (const float*)s_acc;
        float s = 0.0f, sq = 0.0f;
#pragma unroll
        for (int n = 0; n < 16; n++) {
            float v = sa[n * 64 + tid];
            s += v;
            sq += v * v;
        }
        int bucket = blockIdx.x & (NBUCKET - 1);
        atomicAdd(&psums[bucket * 128 + tid], (double)s);
        atomicAdd(&psums[bucket * 128 + HDIM + tid], (double)sq);
    }
}

// ---------------- layer-1 BN finalize ----------------
__global__ void bn_finalize_kernel(const double* __restrict__ psums,
                                   const float* __restrict__ g, const float* __restrict__ be,
                                   float* __restrict__ scale, float* __restrict__ shift) {
    int f = threadIdx.x;
    if (f >= HDIM) return;
    double s = 0.0, sq = 0.0;
#pragma unroll 4
    for (int b = 0; b < NBUCKET; b++) {
        s  += psums[b * 128 + f];
        sq += psums[b * 128 + HDIM + f];
    }
    double mean = s / (double)N_NODES;
    double var  = sq / (double)N_NODES - mean * mean;
    float rs = rsqrtf((float)var + BN_EPS);
    float sc = rs * g[f];
    scale[f] = sc;
    shift[f] = (float)(-mean) * sc + be[f];
}

// ---------------- fused: BN2-finalize + BN1/BN2 apply + residual + pool + MLP head ----
__global__ void __launch_bounds__(512) poolhead_kernel(
        const float* __restrict__ AGG1, const float* __restrict__ AGG2,
        const float* __restrict__ scale1, const float* __restrict__ shift1,
        const double* __restrict__ psums2,
        const float* __restrict__ g2, const float* __restrict__ be2,
        const int* __restrict__ batch,
        const float* __restrict__ lw1, const float* __restrict__ lb1,
        const float* __restrict__ lw2, const float* __restrict__ lb2,
        float* __restrict__ out) {
    int g = blockIdx.x;
    int tid = threadIdx.x;

    __shared__ float sc2s[64], sh2s[64];
    __shared__ int s_start, s_end;

    if (tid >= 64 && tid < 128) {
        int f = tid - 64;
        double s = 0.0, sq = 0.0;
#pragma unroll 4
        for (int b = 0; b < NBUCKET; b++) {
            s  += psums2[b * 128 + f];
            sq += psums2[b * 128 + HDIM + f];
        }
        double mean = s / (double)N_NODES;
        double var  = sq / (double)N_NODES - mean * mean;
        float rs = rsqrtf((float)var + BN_EPS);
        float sc = rs * g2[f];
        sc2s[f] = sc;
        sh2s[f] = (float)(-mean) * sc + be2[f];
    }
    if (tid == 0) {
        int lo = 0, hi = N_NODES;
        while (lo < hi) { int mid = (lo + hi) >> 1; if (batch[mid] < g) lo = mid + 1; else hi = mid; }
        s_start = lo;
        hi = N_NODES;
        while (lo < hi) { int mid = (lo + hi) >> 1; if (batch[mid] < g + 1) lo = mid + 1; else hi = mid; }
        s_end = lo;
    }
    __syncthreads();

    int start = s_start, end = s_end;
    int f = tid & 63;
    int grp = tid >> 6;
    float sc1 = __ldg(scale1 + f), sh1 = __ldg(shift1 + f);
    float sc2 = sc2s[f],           sh2 = sh2s[f];
    float s = 0.0f;
#pragma unroll 2
    for (int r = start + grp; r < end; r += 8) {
        float a1 = AGG1[(size_t)r * 64 + f];
        float a2 = AGG2[(size_t)r * 64 + f];
        s += fmaxf(fmaf(a1, sc1, sh1), 0.0f) + fmaxf(fmaf(a2, sc2, sh2), 0.0f);
    }
    __shared__ float shm[512];
    shm[tid] = s;
    __syncthreads();

    __shared__ float p[64];
    if (grp == 0) {
        float t = 0.0f;
#pragma unroll
        for (int q = 0; q < 8; q++) t += shm[f + q * 64];
        int cnt = end - start;
        p[f] = t / (float)(cnt > 0 ? cnt : 1);
    }
    __syncthreads();

    __shared__ float z[32];
    __shared__ float lg[NCLS];
    if (tid < 32) {
        float acc = lb1[tid];
#pragma unroll
        for (int k = 0; k < 64; k++) acc += p[k] * lw1[k * 32 + tid];
        z[tid] = fmaxf(acc, 0.0f);
    }
    __syncthreads();
    if (tid < NCLS) {
        float acc = lb2[tid];
#pragma unroll
        for (int k = 0; k < 32; k++) acc += z[k] * lw2[k * 10 + tid];
        lg[tid] = acc;
    }
    __syncthreads();
    if (tid == 0) {
        float m = lg[0];
#pragma unroll
        for (int c = 1; c < NCLS; c++) m = fmaxf(m, lg[c]);
        float se = 0.0f;
#pragma unroll
        for (int c = 0; c < NCLS; c++) se += expf(lg[c] - m);
        float l = m + logf(se);
#pragma unroll
        for (int c = 0; c < NCLS; c++) out[g * NCLS + c] = lg[c] - l;
    }
}

// ---------------- host ----------------
extern "C" void kernel_launch(void* const* d_in, const int* in_sizes, int n_in,
                              void* d_out, int out_size) {
    const float* x     = (const float*)d_in[0];
    const int*   ei    = (const int*)  d_in[1];
    const int*   batch = (const int*)  d_in[2];
    const float* W1  = (const float*)d_in[3];
    // b1 (d_in[4]) cancels inside BatchNorm
    const float* g1  = (const float*)d_in[5];
    const float* be1 = (const float*)d_in[6];
    const float* W2  = (const float*)d_in[7];
    // b2 (d_in[8]) cancels
    const float* g2  = (const float*)d_in[9];
    const float* be2 = (const float*)d_in[10];
    const float* lw1 = (const float*)d_in[11];
    const float* lb1 = (const float*)d_in[12];
    const float* lw2 = (const float*)d_in[13];
    const float* lb2 = (const float*)d_in[14];

    const int* src = ei;
    const int* dst = ei + N_EDGES;

    float *buf1, *buf2, *buf3, *dinv, *scale, *shift;
    int *adj, *cnt, *cursor, *localex, *blksum;
    int2* row2;
    double* psums;
    cudaGetSymbolAddress((void**)&buf1,   g_buf1);
    cudaGetSymbolAddress((void**)&buf2,   g_buf2);
    cudaGetSymbolAddress((void**)&buf3,   g_buf3);
    cudaGetSymbolAddress((void**)&adj,    g_adj);
    cudaGetSymbolAddress((void**)&cnt,    g_cnt);
    cudaGetSymbolAddress((void**)&row2,   g_row2);
    cudaGetSymbolAddress((void**)&cursor, g_cursor);
    cudaGetSymbolAddress((void**)&localex,g_localex);
    cudaGetSymbolAddress((void**)&blksum, g_blksum);
    cudaGetSymbolAddress((void**)&dinv,   g_dinv);
    cudaGetSymbolAddress((void**)&psums,  g_psums);
    cudaGetSymbolAddress((void**)&scale,  g_scale);
    cudaGetSymbolAddress((void**)&shift,  g_shift);

    const int TB = 256;
    const int init_blk = (ADJ_TOTAL / 4 + TB - 1) / TB;  // 1563
    const int n_blk    = (N_NODES + TB - 1) / TB;        // 782
    const int e4_blk   = (N_EDGES / 4 + TB - 1) / TB;    // 977
    const int agg_blk  = N_NODES / 16;                   // 12500
    const int gemm_blk = N_NODES / 64;                   // 3125

    // ---- CSR build + norms ----
    init_kernel     <<<init_blk, TB>>>((int4*)adj, cnt, psums, buf1);
    deg_count_kernel<<<e4_blk, TB>>>(dst, cnt);
    scanA_kernel    <<<SCAN_BLKS, 256>>>(cnt, localex, blksum);
    scanC_kernel    <<<n_blk, 256>>>(localex, blksum, cnt, row2, cursor, dinv);
    scatter_kernel  <<<e4_blk, TB>>>(src, dst, cursor, adj);

    // ---- layer 1 ----
    gemm64_kernel<false><<<gemm_blk, TB>>>(x, W1, dinv, nullptr, nullptr, buf1);
    agg_kernel          <<<agg_blk, TB>>>(row2, adj, dinv, buf1, buf2, psums);
    bn_finalize_kernel  <<<1, 64>>>(psums, g1, be1, scale, shift);

    // ---- layer 2 (BN1+relu fused into gemm input load) ----
    gemm64_kernel<true> <<<gemm_blk, TB>>>(buf2, W2, dinv, scale, shift, buf1);
    agg_kernel          <<<agg_blk, TB>>>(row2, adj, dinv, buf1, buf3, psums + PSUM_STRIDE);

    // ---- fused BN2-finalize + BN-apply(x2) + residual + pool + head ----
    poolhead_kernel<<<NGRAPH, 512>>>(buf2, buf3, scale, shift, psums + PSUM_STRIDE,
                                     g2, be2, batch, lw1, lb1, lw2, lb2, (float*)d_out);
}